// round 3
// baseline (speedup 1.0000x reference)
#include <cuda_runtime.h>
#include <math.h>

#define BB 2
#define CC 4
#define FF 512
#define NN 1000
#define NP 1024
#define TAPS 5
#define NITER 5
#define FSPLIT 32
#define FPER (FF / FSPLIT)
#define EPSV 1e-3f
#define LAP_EPS 1e-5f
#define INV_NF (1.0f / 1000.0f)
#define XS 1032  /* smem X stride per channel (float2), covers j in [0,1031] */
#define NTHR 256

// ---------------- global scratch (static __device__ arrays; no allocation) --
__device__ float2 g_Y[BB][CC][FF][NP];          // ~33.6 MB, n padded to 1024 (pad stays 0)
__device__ float  g_spart[BB][CC][FSPLIT][NP];  // 1 MB partial |Y|^2 sums over f-splits
__device__ float  g_w[BB][CC][NP];              // effective weights (g folded in), pad = 0
__device__ float  g_ysc[BB][CC];                // 1/sqrt(g) per (b,c)

// ---------------- init: Y0 = W0 @ X, W0 = eye maxed with EPS ----------------
// Y0[c] = 0.999*X[c] + 0.001*sum_d X[d]
__global__ void k_init(const float* __restrict__ xr, const float* __restrict__ xi) {
    int f = blockIdx.x, b = blockIdx.y;
    int t = threadIdx.x;
    for (int n = t; n < NP; n += NTHR) {
        if (n < NN) {
            float re[CC], im[CC], sr = 0.f, si = 0.f;
            #pragma unroll
            for (int c = 0; c < CC; c++) {
                size_t idx = ((size_t)(b * CC + c) * FF + f) * NN + n;
                re[c] = xr[idx]; im[c] = xi[idx];
                sr += re[c]; si += im[c];
            }
            #pragma unroll
            for (int c = 0; c < CC; c++) {
                g_Y[b][c][f][n] = make_float2(0.999f * re[c] + 0.001f * sr,
                                              0.999f * im[c] + 0.001f * si);
            }
        } else {
            #pragma unroll
            for (int c = 0; c < CC; c++) g_Y[b][c][f][n] = make_float2(0.f, 0.f);
        }
    }
}

// ---------------- phase A1: partial sums over f of |Y|^2 --------------------
__global__ void k_spart() {
    int fs = blockIdx.x, c = blockIdx.y, b = blockIdx.z;
    int t = threadIdx.x;
    float acc[4] = {0.f, 0.f, 0.f, 0.f};
    for (int fo = 0; fo < FPER; fo++) {
        int f = fs * FPER + fo;
        #pragma unroll
        for (int k = 0; k < 4; k++) {
            float2 y = g_Y[b][c][f][t + NTHR * k];
            acc[k] = fmaf(y.x, y.x, fmaf(y.y, y.y, acc[k]));
        }
    }
    #pragma unroll
    for (int k = 0; k < 4; k++) g_spart[b][c][fs][t + NTHR * k] = acc[k];
}

// ---------------- phase A2: g, weights, yscale ------------------------------
__global__ void k_weights() {
    int c = blockIdx.x, b = blockIdx.y;
    int t = threadIdx.x;
    __shared__ float red[NTHR];
    float s[4];
    float tot = 0.f;
    #pragma unroll
    for (int k = 0; k < 4; k++) {
        float a = 0.f;
        for (int fs = 0; fs < FSPLIT; fs++) a += g_spart[b][c][fs][t + NTHR * k];
        s[k] = a;
        tot += a;  // pad entries are exactly 0 (Y pad never written)
    }
    red[t] = tot;
    __syncthreads();
    for (int off = NTHR / 2; off; off >>= 1) {
        if (t < off) red[t] += red[t + off];
        __syncthreads();
    }
    float g = fmaxf(red[0] * (1.0f / ((float)FF * (float)NN)), EPSV);
    #pragma unroll
    for (int k = 0; k < 4; k++) {
        int n = t + NTHR * k;
        float w = (n < NN) ? g / fmaxf(2.0f * sqrtf(s[k]), LAP_EPS) : 0.0f;
        g_w[b][c][n] = w;
    }
    if (t == 0) g_ysc[b][c] = 1.0f / sqrtf(g);  // g >= 1e-3 so sqrt(g) > EPS
}

// ---------------- block reduce of (v_num[c], v_den[c]) -> v[c] --------------
__device__ __forceinline__ void block_reduce_v(
    float nr[4], float ni[4], float dd[4],
    float (*red)[12], float2* v_sm, int t, bool iss, int src)
{
    #pragma unroll
    for (int off = 16; off; off >>= 1) {
        #pragma unroll
        for (int c = 0; c < 4; c++) {
            nr[c] += __shfl_xor_sync(0xffffffffu, nr[c], off);
            ni[c] += __shfl_xor_sync(0xffffffffu, ni[c], off);
            dd[c] += __shfl_xor_sync(0xffffffffu, dd[c], off);
        }
    }
    if ((t & 31) == 0) {
        int w = t >> 5;
        #pragma unroll
        for (int c = 0; c < 4; c++) {
            red[w][c * 3 + 0] = nr[c];
            red[w][c * 3 + 1] = ni[c];
            red[w][c * 3 + 2] = dd[c];
        }
    }
    __syncthreads();
    if (t < 4) {
        float a = 0.f, bI = 0.f, d = 0.f;
        #pragma unroll
        for (int w = 0; w < NTHR / 32; w++) {
            a  += red[w][t * 3 + 0];
            bI += red[w][t * 3 + 1];
            d  += red[w][t * 3 + 2];
        }
        float sc = iss ? INV_NF : 1.0f;
        float den = fmaxf(d * sc, EPSV);
        float vr, vi;
        if (iss && t == src) {
            vr = 1.0f - 1.0f / sqrtf(den);
            vi = 0.0f;
        } else {
            float inv = sc / den;
            vr = a * inv;
            vi = bI * inv;
        }
        v_sm[t] = make_float2(vr, vi);
    }
    __syncthreads();
}

// ---------------- phase B: one full ISS+WPE iteration per (b,f) CTA ---------
__global__ void __launch_bounds__(NTHR) k_iter(const float* __restrict__ xr,
                                               const float* __restrict__ xi) {
    int f = blockIdx.x, b = blockIdx.y;
    int t = threadIdx.x;
    __shared__ float2 x_sm[CC][XS];
    __shared__ float red[NTHR / 32][12];
    __shared__ float2 v_sm[CC];

    // zero only the pad regions of x_sm: j in [0,6) and [1006, XS)
    if (t < 128) {
        int c = t >> 5;
        int j = t & 31;
        int idx = (j < 6) ? j : (1000 + j);  // 1006..1031
        x_sm[c][idx] = make_float2(0.f, 0.f);
    }
    // fill x_sm[c][n+6] = X[b,c,f,n] (delayed taps Z[n] = x_sm[src][n+tap])
    float ysc[CC];
    #pragma unroll
    for (int c = 0; c < CC; c++) {
        size_t base = ((size_t)(b * CC + c) * FF + f) * NN;
        for (int n = t; n < NN; n += NTHR)
            x_sm[c][n + 6] = make_float2(xr[base + n], xi[base + n]);
        ysc[c] = g_ysc[b][c];
    }
    // Y (scaled by 1/sqrt(g)) and weights into registers: 4 frames per thread
    float Yr[CC][4], Yi[CC][4], W[CC][4];
    #pragma unroll
    for (int c = 0; c < CC; c++) {
        #pragma unroll
        for (int k = 0; k < 4; k++) {
            int n = t + NTHR * k;  // <= 1023, padded array
            float2 y = g_Y[b][c][f][n];
            Yr[c][k] = y.x * ysc[c];
            Yi[c][k] = y.y * ysc[c];
            W[c][k] = g_w[b][c][n];  // pad -> 0
        }
    }
    __syncthreads();

    // ---- ISS source steps (src compile-time: Y indexed by src) ----
    #pragma unroll
    for (int src = 0; src < CC; src++) {
        float nr[4] = {0, 0, 0, 0}, ni[4] = {0, 0, 0, 0}, dd[4] = {0, 0, 0, 0};
        #pragma unroll
        for (int k = 0; k < 4; k++) {
            float zr = Yr[src][k], zi = Yi[src][k];
            float r = zr * zr + zi * zi;
            #pragma unroll
            for (int c = 0; c < CC; c++) {
                float p = Yr[c][k] * zr + Yi[c][k] * zi;   // Re(Y * conj(Z))
                float q = Yi[c][k] * zr - Yr[c][k] * zi;   // Im(Y * conj(Z))
                nr[c] = fmaf(W[c][k], p, nr[c]);
                ni[c] = fmaf(W[c][k], q, ni[c]);
                dd[c] = fmaf(W[c][k], r, dd[c]);
            }
        }
        block_reduce_v(nr, ni, dd, red, v_sm, t, true, src);
        float2 v[CC];
        #pragma unroll
        for (int c = 0; c < CC; c++) v[c] = v_sm[c];
        #pragma unroll
        for (int k = 0; k < 4; k++) {
            float zr = Yr[src][k], zi = Yi[src][k];  // snapshot before update
            #pragma unroll
            for (int c = 0; c < CC; c++) {
                Yr[c][k] -= v[c].x * zr - v[c].y * zi;
                Yi[c][k] -= v[c].x * zi + v[c].y * zr;
            }
        }
    }

    // ---- WPE tap steps (Z from smem; src/tap runtime) ----
    for (int src = 0; src < CC; src++) {
        for (int tap = 0; tap < TAPS; tap++) {
            float nr[4] = {0, 0, 0, 0}, ni[4] = {0, 0, 0, 0}, dd[4] = {0, 0, 0, 0};
            float zr_[4], zi_[4];
            #pragma unroll
            for (int k = 0; k < 4; k++) {
                float2 z = x_sm[src][t + NTHR * k + tap];
                zr_[k] = z.x; zi_[k] = z.y;
                float r = z.x * z.x + z.y * z.y;
                #pragma unroll
                for (int c = 0; c < CC; c++) {
                    float p = Yr[c][k] * z.x + Yi[c][k] * z.y;
                    float q = Yi[c][k] * z.x - Yr[c][k] * z.y;
                    nr[c] = fmaf(W[c][k], p, nr[c]);
                    ni[c] = fmaf(W[c][k], q, ni[c]);
                    dd[c] = fmaf(W[c][k], r, dd[c]);
                }
            }
            block_reduce_v(nr, ni, dd, red, v_sm, t, false, 0);
            float2 v[CC];
            #pragma unroll
            for (int c = 0; c < CC; c++) v[c] = v_sm[c];
            #pragma unroll
            for (int k = 0; k < 4; k++) {
                #pragma unroll
                for (int c = 0; c < CC; c++) {
                    Yr[c][k] -= v[c].x * zr_[k] - v[c].y * zi_[k];
                    Yi[c][k] -= v[c].x * zi_[k] + v[c].y * zr_[k];
                }
            }
        }
    }

    // ---- store (never touch pad n >= 1000 so it stays 0) ----
    #pragma unroll
    for (int c = 0; c < CC; c++) {
        #pragma unroll
        for (int k = 0; k < 4; k++) {
            int n = t + NTHR * k;
            if (n < NN) g_Y[b][c][f][n] = make_float2(Yr[c][k], Yi[c][k]);
        }
    }
}

// ---------------- output: deinterleave to (2, B, C, F, N) -------------------
__global__ void k_out(float* __restrict__ out) {
    int f = blockIdx.x, c = blockIdx.y, b = blockIdx.z;
    int t = threadIdx.x;
    size_t ob = ((size_t)(b * CC + c) * FF + f) * NN;
    const size_t half = (size_t)BB * CC * FF * NN;
    for (int n = t; n < NN; n += NTHR) {
        float2 y = g_Y[b][c][f][n];
        out[ob + n] = y.x;
        out[half + ob + n] = y.y;
    }
}

extern "C" void kernel_launch(void* const* d_in, const int* in_sizes, int n_in,
                              void* d_out, int out_size) {
    const float* xr = (const float*)d_in[0];
    const float* xi = (const float*)d_in[1];
    float* out = (float*)d_out;

    k_init<<<dim3(FF, BB), NTHR>>>(xr, xi);
    for (int it = 0; it < NITER; it++) {
        k_spart<<<dim3(FSPLIT, CC, BB), NTHR>>>();
        k_weights<<<dim3(CC, BB), NTHR>>>();
        k_iter<<<dim3(FF, BB), NTHR>>>(xr, xi);
    }
    k_out<<<dim3(FF, CC, BB), NTHR>>>(out);
}

// round 6
// speedup vs baseline: 1.0031x; 1.0031x over previous
#include <cuda_runtime.h>
#include <math.h>

#define BB 2
#define CC 4
#define FF 512
#define NN 1000
#define NP 1024
#define TAPS 5
#define NITER 5
#define FSPLIT 32
#define FPER (FF / FSPLIT)
#define EPSV 1e-3f
#define LAP_EPS 1e-5f
#define INV_NF (1.0f / 1000.0f)
#define XS 1032
#define NTHR 256

typedef unsigned long long u64;

// ---------------- f32x2 helpers (packed fp32, sm_100) -----------------------
__device__ __forceinline__ u64 pk2(float lo, float hi) {
    u64 r; asm("mov.b64 %0, {%1, %2};" : "=l"(r) : "f"(lo), "f"(hi)); return r;
}
__device__ __forceinline__ void upk2(u64 v, float& lo, float& hi) {
    asm("mov.b64 {%0, %1}, %2;" : "=f"(lo), "=f"(hi) : "l"(v));
}
__device__ __forceinline__ u64 mul2(u64 a, u64 b) {
    u64 d; asm("mul.rn.f32x2 %0, %1, %2;" : "=l"(d) : "l"(a), "l"(b)); return d;
}
__device__ __forceinline__ u64 fma2(u64 a, u64 b, u64 c) {
    u64 d; asm("fma.rn.f32x2 %0, %1, %2, %3;" : "=l"(d) : "l"(a), "l"(b), "l"(c)); return d;
}

// ---------------- global scratch --------------------------------------------
__device__ float2 g_Y[BB][CC][FF][NP];
__device__ float  g_spart[BB][CC][FSPLIT][NP];
__device__ float  g_w[BB][CC][NP];
__device__ float  g_ysc[BB][CC];

// ---------------- init: Y0[c] = 0.999*X[c] + 0.001*sum_d X[d] ---------------
__global__ void k_init(const float* __restrict__ xr, const float* __restrict__ xi) {
    int f = blockIdx.x, b = blockIdx.y;
    int t = threadIdx.x;
    for (int n = t; n < NP; n += NTHR) {
        if (n < NN) {
            float re[CC], im[CC], sr = 0.f, si = 0.f;
            #pragma unroll
            for (int c = 0; c < CC; c++) {
                size_t idx = ((size_t)(b * CC + c) * FF + f) * NN + n;
                re[c] = xr[idx]; im[c] = xi[idx];
                sr += re[c]; si += im[c];
            }
            #pragma unroll
            for (int c = 0; c < CC; c++)
                g_Y[b][c][f][n] = make_float2(0.999f * re[c] + 0.001f * sr,
                                              0.999f * im[c] + 0.001f * si);
        } else {
            #pragma unroll
            for (int c = 0; c < CC; c++) g_Y[b][c][f][n] = make_float2(0.f, 0.f);
        }
    }
}

// ---------------- phase A1: partial sums over f of |Y|^2 --------------------
__global__ void k_spart() {
    int fs = blockIdx.x, c = blockIdx.y, b = blockIdx.z;
    int t = threadIdx.x;
    float acc[4] = {0.f, 0.f, 0.f, 0.f};
    for (int fo = 0; fo < FPER; fo++) {
        int f = fs * FPER + fo;
        #pragma unroll
        for (int k = 0; k < 4; k++) {
            float2 y = g_Y[b][c][f][t + NTHR * k];
            acc[k] = fmaf(y.x, y.x, fmaf(y.y, y.y, acc[k]));
        }
    }
    #pragma unroll
    for (int k = 0; k < 4; k++) g_spart[b][c][fs][t + NTHR * k] = acc[k];
}

// ---------------- phase A2: g, weights, yscale ------------------------------
__global__ void k_weights() {
    int c = blockIdx.x, b = blockIdx.y;
    int t = threadIdx.x;
    __shared__ float red[NTHR];
    float s[4];
    float tot = 0.f;
    #pragma unroll
    for (int k = 0; k < 4; k++) {
        float a = 0.f;
        for (int fs = 0; fs < FSPLIT; fs++) a += g_spart[b][c][fs][t + NTHR * k];
        s[k] = a;
        tot += a;
    }
    red[t] = tot;
    __syncthreads();
    for (int off = NTHR / 2; off; off >>= 1) {
        if (t < off) red[t] += red[t + off];
        __syncthreads();
    }
    float g = fmaxf(red[0] * (1.0f / ((float)FF * (float)NN)), EPSV);
    #pragma unroll
    for (int k = 0; k < 4; k++) {
        int n = t + NTHR * k;
        float w = (n < NN) ? g / fmaxf(2.0f * sqrtf(s[k]), LAP_EPS) : 0.0f;
        g_w[b][c][n] = w;
    }
    if (t == 0) g_ysc[b][c] = 1.0f / sqrtf(g);
}

// ---------------- block reduce: 12 partials -> v broadcast ------------------
__device__ __forceinline__ void block_reduce_v(
    float nr[4], float ni[4], float dd[4],
    float (*red)[12], float2* v_sm, int t, bool iss, int src)
{
    #pragma unroll
    for (int off = 16; off; off >>= 1) {
        #pragma unroll
        for (int c = 0; c < 4; c++) {
            nr[c] += __shfl_xor_sync(0xffffffffu, nr[c], off);
            ni[c] += __shfl_xor_sync(0xffffffffu, ni[c], off);
            dd[c] += __shfl_xor_sync(0xffffffffu, dd[c], off);
        }
    }
    if ((t & 31) == 0) {
        int w = t >> 5;
        #pragma unroll
        for (int c = 0; c < 4; c++) {
            red[w][c * 3 + 0] = nr[c];
            red[w][c * 3 + 1] = ni[c];
            red[w][c * 3 + 2] = dd[c];
        }
    }
    __syncthreads();
    if (t < 4) {
        float a = 0.f, bI = 0.f, d = 0.f;
        #pragma unroll
        for (int w = 0; w < NTHR / 32; w++) {
            a  += red[w][t * 3 + 0];
            bI += red[w][t * 3 + 1];
            d  += red[w][t * 3 + 2];
        }
        float sc = iss ? INV_NF : 1.0f;
        float den = fmaxf(d * sc, EPSV);
        float vr, vi;
        if (iss && t == src) {
            vr = 1.0f - 1.0f / sqrtf(den);
            vi = 0.0f;
        } else {
            float inv = sc / den;
            vr = a * inv;
            vi = bI * inv;
        }
        v_sm[t] = make_float2(vr, vi);
    }
    __syncthreads();
}

// ---------------- phase B: one full ISS+WPE iteration per (b,f) CTA ---------
// Frames packed as f32x2 pairs: kk=0 -> (n=t, n=t+256), kk=1 -> (t+512, t+768)
__global__ void __launch_bounds__(NTHR, 3) k_iter(const float* __restrict__ xr,
                                                  const float* __restrict__ xi) {
    int f = blockIdx.x, b = blockIdx.y;
    int t = threadIdx.x;
    __shared__ float2 x_sm[CC][XS];
    __shared__ float red[NTHR / 32][12];
    __shared__ float2 v_sm[CC];

    const u64 NEG1 = pk2(-1.0f, -1.0f);

    // zero pad regions of x_sm: j in [0,6) and [1006, XS)
    if (t < 128) {
        int c = t >> 5;
        int j = t & 31;
        int idx = (j < 6) ? j : (1000 + j);
        x_sm[c][idx] = make_float2(0.f, 0.f);
    }
    float ysc[CC];
    #pragma unroll
    for (int c = 0; c < CC; c++) {
        size_t base = ((size_t)(b * CC + c) * FF + f) * NN;
        for (int n = t; n < NN; n += NTHR)
            x_sm[c][n + 6] = make_float2(xr[base + n], xi[base + n]);
        ysc[c] = g_ysc[b][c];
    }

    // Y (scaled) and W into packed registers
    u64 Yr2[CC][2], Yi2[CC][2], W2[CC][2];
    #pragma unroll
    for (int c = 0; c < CC; c++) {
        #pragma unroll
        for (int kk = 0; kk < 2; kk++) {
            int n0 = t + 512 * kk, n1 = n0 + 256;
            float2 y0 = g_Y[b][c][f][n0];
            float2 y1 = g_Y[b][c][f][n1];
            Yr2[c][kk] = pk2(y0.x * ysc[c], y1.x * ysc[c]);
            Yi2[c][kk] = pk2(y0.y * ysc[c], y1.y * ysc[c]);
            W2[c][kk]  = pk2(g_w[b][c][n0], g_w[b][c][n1]);
        }
    }
    __syncthreads();

    // ---- ISS source steps ----
    #pragma unroll
    for (int src = 0; src < CC; src++) {
        u64 zr2[2], zi2[2], r2k[2];
        #pragma unroll
        for (int kk = 0; kk < 2; kk++) {
            zr2[kk] = Yr2[src][kk];
            zi2[kk] = Yi2[src][kk];
            r2k[kk] = fma2(zi2[kk], zi2[kk], mul2(zr2[kk], zr2[kk]));
        }
        u64 nr2[4], ni2[4], dd2[4];
        #pragma unroll
        for (int c = 0; c < CC; c++) { nr2[c] = 0; ni2[c] = 0; dd2[c] = 0; }
        #pragma unroll
        for (int c = 0; c < CC; c++) {
            #pragma unroll
            for (int kk = 0; kk < 2; kk++) {
                u64 p2 = fma2(Yi2[c][kk], zi2[kk], mul2(Yr2[c][kk], zr2[kk]));
                u64 t2 = mul2(Yr2[c][kk], zi2[kk]);
                u64 q2 = fma2(t2, NEG1, mul2(Yi2[c][kk], zr2[kk]));
                nr2[c] = fma2(W2[c][kk], p2, nr2[c]);
                ni2[c] = fma2(W2[c][kk], q2, ni2[c]);
                dd2[c] = fma2(W2[c][kk], r2k[kk], dd2[c]);
            }
        }
        float nr[4], ni[4], dd[4];
        #pragma unroll
        for (int c = 0; c < CC; c++) {
            float lo, hi;
            upk2(nr2[c], lo, hi); nr[c] = lo + hi;
            upk2(ni2[c], lo, hi); ni[c] = lo + hi;
            upk2(dd2[c], lo, hi); dd[c] = lo + hi;
        }
        block_reduce_v(nr, ni, dd, red, v_sm, t, true, src);
        #pragma unroll
        for (int c = 0; c < CC; c++) {
            float2 vv = v_sm[c];
            u64 vrn = pk2(-vv.x, -vv.x);
            u64 vip = pk2(vv.y, vv.y);
            u64 vin = pk2(-vv.y, -vv.y);
            #pragma unroll
            for (int kk = 0; kk < 2; kk++) {
                Yr2[c][kk] = fma2(vrn, zr2[kk], fma2(vip, zi2[kk], Yr2[c][kk]));
                Yi2[c][kk] = fma2(vrn, zi2[kk], fma2(vin, zr2[kk], Yi2[c][kk]));
            }
        }
    }

    // ---- WPE tap steps ----
    for (int src = 0; src < CC; src++) {
        for (int tap = 0; tap < TAPS; tap++) {
            int j0 = t + tap;
            u64 zr2[2], zi2[2], r2k[2];
            #pragma unroll
            for (int kk = 0; kk < 2; kk++) {
                float2 a0 = x_sm[src][j0 + 512 * kk];
                float2 a1 = x_sm[src][j0 + 512 * kk + 256];
                zr2[kk] = pk2(a0.x, a1.x);
                zi2[kk] = pk2(a0.y, a1.y);
                r2k[kk] = fma2(zi2[kk], zi2[kk], mul2(zr2[kk], zr2[kk]));
            }
            u64 nr2[4], ni2[4], dd2[4];
            #pragma unroll
            for (int c = 0; c < CC; c++) { nr2[c] = 0; ni2[c] = 0; dd2[c] = 0; }
            #pragma unroll
            for (int c = 0; c < CC; c++) {
                #pragma unroll
                for (int kk = 0; kk < 2; kk++) {
                    u64 p2 = fma2(Yi2[c][kk], zi2[kk], mul2(Yr2[c][kk], zr2[kk]));
                    u64 t2 = mul2(Yr2[c][kk], zi2[kk]);
                    u64 q2 = fma2(t2, NEG1, mul2(Yi2[c][kk], zr2[kk]));
                    nr2[c] = fma2(W2[c][kk], p2, nr2[c]);
                    ni2[c] = fma2(W2[c][kk], q2, ni2[c]);
                    dd2[c] = fma2(W2[c][kk], r2k[kk], dd2[c]);
                }
            }
            float nr[4], ni[4], dd[4];
            #pragma unroll
            for (int c = 0; c < CC; c++) {
                float lo, hi;
                upk2(nr2[c], lo, hi); nr[c] = lo + hi;
                upk2(ni2[c], lo, hi); ni[c] = lo + hi;
                upk2(dd2[c], lo, hi); dd[c] = lo + hi;
            }
            block_reduce_v(nr, ni, dd, red, v_sm, t, false, 0);
            #pragma unroll
            for (int c = 0; c < CC; c++) {
                float2 vv = v_sm[c];
                u64 vrn = pk2(-vv.x, -vv.x);
                u64 vip = pk2(vv.y, vv.y);
                u64 vin = pk2(-vv.y, -vv.y);
                #pragma unroll
                for (int kk = 0; kk < 2; kk++) {
                    Yr2[c][kk] = fma2(vrn, zr2[kk], fma2(vip, zi2[kk], Yr2[c][kk]));
                    Yi2[c][kk] = fma2(vrn, zi2[kk], fma2(vin, zr2[kk], Yi2[c][kk]));
                }
            }
        }
    }

    // ---- store (pad n >= 1000 untouched, stays 0) ----
    #pragma unroll
    for (int c = 0; c < CC; c++) {
        #pragma unroll
        for (int kk = 0; kk < 2; kk++) {
            float r0, r1, i0, i1;
            upk2(Yr2[c][kk], r0, r1);
            upk2(Yi2[c][kk], i0, i1);
            int n0 = t + 512 * kk, n1 = n0 + 256;
            if (n0 < NN) g_Y[b][c][f][n0] = make_float2(r0, i0);
            if (n1 < NN) g_Y[b][c][f][n1] = make_float2(r1, i1);
        }
    }
}

// ---------------- output: (2, B, C, F, N) -----------------------------------
__global__ void k_out(float* __restrict__ out) {
    int f = blockIdx.x, c = blockIdx.y, b = blockIdx.z;
    int t = threadIdx.x;
    size_t ob = ((size_t)(b * CC + c) * FF + f) * NN;
    const size_t half = (size_t)BB * CC * FF * NN;
    for (int n = t; n < NN; n += NTHR) {
        float2 y = g_Y[b][c][f][n];
        out[ob + n] = y.x;
        out[half + ob + n] = y.y;
    }
}

extern "C" void kernel_launch(void* const* d_in, const int* in_sizes, int n_in,
                              void* d_out, int out_size) {
    const float* xr = (const float*)d_in[0];
    const float* xi = (const float*)d_in[1];
    float* out = (float*)d_out;

    k_init<<<dim3(FF, BB), NTHR>>>(xr, xi);
    for (int it = 0; it < NITER; it++) {
        k_spart<<<dim3(FSPLIT, CC, BB), NTHR>>>();
        k_weights<<<dim3(CC, BB), NTHR>>>();
        k_iter<<<dim3(FF, BB), NTHR>>>(xr, xi);
    }
    k_out<<<dim3(FF, CC, BB), NTHR>>>(out);
}